// round 3
// baseline (speedup 1.0000x reference)
#include <cuda_runtime.h>

// Problem-shape maxima (fixed by the dataset)
#define NMAX   50000
#define EMAX   800000
#define ETMAX  (EMAX + NMAX)      // edges + self loops
#define HEADS  4
#define HC1    128                // heads * 32
#define HC2    256                // heads * 64
#define NEG_SLOPE 0.2f
#define GAT_EPS 1e-16f

// ---------------- scratch (static device globals; no allocation) ------------
__device__ float g_h1 [NMAX * HC1];   // layer1 linear output
__device__ float g_acc1[NMAX * HC1];  // layer1 scatter accumulator -> y1 (elu)
__device__ float g_h2 [NMAX * HC2];   // layer2 linear output
__device__ float g_acc2[NMAX * HC2];  // layer2 scatter accumulator
__device__ float g_asrc[NMAX * HEADS];
__device__ float g_adst[NMAX * HEADS];
__device__ float g_max [NMAX * HEADS];
__device__ float g_sum [NMAX * HEADS];
__device__ float g_e   [ETMAX * HEADS]; // exp(logit - max) per edge/head
__device__ int   g_is64;                // 1 if edge_index is int64 on device

// ---------------- helpers ---------------------------------------------------
__device__ __forceinline__ float lrelu(float x) {
    return x > 0.0f ? x : NEG_SLOPE * x;
}

// edge_index element fetch, dtype decided at runtime by g_is64
__device__ __forceinline__ int eidx(const int* __restrict__ ei, int is64, long long pos) {
    if (is64) return (int)((const long long*)ei)[pos];
    return ei[pos];
}

// float atomic max via ordered-int trick (init must be -inf)
__device__ __forceinline__ void atomicMaxFloat(float* addr, float val) {
    if (val >= 0.0f) {
        atomicMax((int*)addr, __float_as_int(val));
    } else {
        atomicMin((unsigned int*)addr, __float_as_uint(val));
    }
}

__device__ __forceinline__ void red_add_v4(float* p, float4 v) {
    asm volatile("red.global.add.v4.f32 [%0], {%1, %2, %3, %4};"
                 :: "l"(p), "f"(v.x), "f"(v.y), "f"(v.z), "f"(v.w)
                 : "memory");
}

// ---------------- dtype detection -------------------------------------------
// If data is int64 (values in [0, 50000)), every odd 32-bit word (high half)
// is zero. With int32 data, odd words are node indices (nonzero w.h.p. over
// 8K samples). Single block; writes g_is64 each call (deterministic).
__global__ void detect_kernel(const unsigned int* __restrict__ w, long long nWords) {
    __shared__ int s_nz;
    if (threadIdx.x == 0) s_nz = 0;
    __syncthreads();
    long long limit = nWords < 16384 ? nWords : 16384;
    int nz = 0;
    for (long long i = 1 + 2LL * threadIdx.x; i < limit; i += 2LL * blockDim.x)
        nz |= (w[i] != 0u);
    if (nz) atomicOr(&s_nz, 1);
    __syncthreads();
    if (threadIdx.x == 0) g_is64 = (s_nz == 0) ? 1 : 0;
}

// ---------------- GEMM: Y[M,NOUT] = X[M,128] @ W[128,NOUT] ------------------
template<int NOUT, int ROWS>
__global__ void gemm_kernel(const float* __restrict__ X,
                            const float* __restrict__ W,
                            float* __restrict__ Y, int M) {
    __shared__ float xs[ROWS][128];
    const int row0 = blockIdx.x * ROWS;
    const int tid  = threadIdx.x;          // one output column per thread

    for (int i = tid; i < ROWS * 128; i += NOUT) {
        int r = i >> 7, k = i & 127;
        xs[r][k] = (row0 + r < M) ? X[(size_t)(row0 + r) * 128 + k] : 0.0f;
    }
    __syncthreads();

    float acc[ROWS];
#pragma unroll
    for (int r = 0; r < ROWS; r++) acc[r] = 0.0f;

#pragma unroll 4
    for (int k = 0; k < 128; k++) {
        float w = __ldg(&W[k * NOUT + tid]);
#pragma unroll
        for (int r = 0; r < ROWS; r++) acc[r] = fmaf(xs[r][k], w, acc[r]);
    }

#pragma unroll
    for (int r = 0; r < ROWS; r++)
        if (row0 + r < M) Y[(size_t)(row0 + r) * NOUT + tid] = acc[r];
}

// ---------------- per-node attention coefficients ---------------------------
// a_src[n,h] = sum_c h[n,h,c]*att_src[h,c]   (block = 1 node, HC threads)
template<int HC>
__global__ void att_kernel(const float* __restrict__ H,
                           const float* __restrict__ av_src,
                           const float* __restrict__ av_dst,
                           float* __restrict__ osrc,
                           float* __restrict__ odst) {
    const int n = blockIdx.x;
    const int t = threadIdx.x;
    float v  = H[(size_t)n * HC + t];
    float ps = v * av_src[t];
    float pd = v * av_dst[t];
#pragma unroll
    for (int o = 16; o > 0; o >>= 1) {
        ps += __shfl_down_sync(0xffffffffu, ps, o);
        pd += __shfl_down_sync(0xffffffffu, pd, o);
    }
    __shared__ float ss[HC / 32], sd[HC / 32];
    if ((t & 31) == 0) { ss[t >> 5] = ps; sd[t >> 5] = pd; }
    __syncthreads();
    constexpr int WPH = (HC / HEADS) / 32;   // warps per head
    if (t < HEADS) {
        float s = 0.0f, d = 0.0f;
#pragma unroll
        for (int w = 0; w < WPH; w++) { s += ss[t * WPH + w]; d += sd[t * WPH + w]; }
        osrc[n * HEADS + t] = s;
        odst[n * HEADS + t] = d;
    }
}

// ---------------- init accumulators / max / sum -----------------------------
__global__ void init_kernel(float* __restrict__ acc, int nAcc,
                            float* __restrict__ mx, float* __restrict__ sm, int nMS) {
    int i = blockIdx.x * blockDim.x + threadIdx.x;
    if (i < nAcc) acc[i] = 0.0f;
    if (i < nMS) { mx[i] = __int_as_float(0xff800000); sm[i] = 0.0f; }
}

// ---------------- edge pass 1: segment max ----------------------------------
__global__ void edge_max_kernel(const int* __restrict__ ei, int E, int Nn,
                                const float* __restrict__ asrc,
                                const float* __restrict__ adst,
                                float* __restrict__ mx) {
    int e = blockIdx.x * blockDim.x + threadIdx.x;
    int Et = E + Nn;
    if (e >= Et) return;
    int is64 = g_is64;
    int s, d;
    if (e < E) { s = eidx(ei, is64, e); d = eidx(ei, is64, (long long)E + e); }
    else       { s = d = e - E; }
    float4 as = ((const float4*)asrc)[s];
    float4 ad = ((const float4*)adst)[d];
    atomicMaxFloat(&mx[d * 4 + 0], lrelu(as.x + ad.x));
    atomicMaxFloat(&mx[d * 4 + 1], lrelu(as.y + ad.y));
    atomicMaxFloat(&mx[d * 4 + 2], lrelu(as.z + ad.z));
    atomicMaxFloat(&mx[d * 4 + 3], lrelu(as.w + ad.w));
}

// ---------------- edge pass 2: exp + segment sum ----------------------------
__global__ void edge_sum_kernel(const int* __restrict__ ei, int E, int Nn,
                                const float* __restrict__ asrc,
                                const float* __restrict__ adst,
                                const float* __restrict__ mx,
                                float* __restrict__ ebuf,
                                float* __restrict__ sm) {
    int e = blockIdx.x * blockDim.x + threadIdx.x;
    int Et = E + Nn;
    if (e >= Et) return;
    int is64 = g_is64;
    int s, d;
    if (e < E) { s = eidx(ei, is64, e); d = eidx(ei, is64, (long long)E + e); }
    else       { s = d = e - E; }
    float4 as = ((const float4*)asrc)[s];
    float4 ad = ((const float4*)adst)[d];
    float4 m  = ((const float4*)mx)[d];
    float4 ev;
    ev.x = expf(lrelu(as.x + ad.x) - m.x);
    ev.y = expf(lrelu(as.y + ad.y) - m.y);
    ev.z = expf(lrelu(as.z + ad.z) - m.z);
    ev.w = expf(lrelu(as.w + ad.w) - m.w);
    ((float4*)ebuf)[e] = ev;
    red_add_v4(&sm[d * 4], ev);
}

// ---------------- edge pass 3: weighted scatter-add -------------------------
// LPE lanes per edge; lane L handles float4 at channel offset L*4 of HC.
template<int HC, int LPE>
__global__ void edge_scatter_kernel(const int* __restrict__ ei, int E, int Nn,
                                    const float* __restrict__ H,
                                    const float* __restrict__ ebuf,
                                    const float* __restrict__ sm,
                                    float* __restrict__ acc) {
    int gt = blockIdx.x * blockDim.x + threadIdx.x;
    int e  = gt / LPE;
    int L  = gt % LPE;
    int Et = E + Nn;
    if (e >= Et) return;
    int is64 = g_is64;
    int s, d;
    if (e < E) { s = eidx(ei, is64, e); d = eidx(ei, is64, (long long)E + e); }
    else       { s = d = e - E; }
    constexpr int CH = HC / HEADS;
    const int head = (L * 4) / CH;
    float ev = __ldg(&ebuf[e * 4 + head]);
    float sv = __ldg(&sm[d * 4 + head]);
    float alpha = ev / (sv + GAT_EPS);
    float4 hv = ((const float4*)(H + (size_t)s * HC))[L];
    float4 o;
    o.x = alpha * hv.x; o.y = alpha * hv.y; o.z = alpha * hv.z; o.w = alpha * hv.w;
    red_add_v4(acc + (size_t)d * HC + L * 4, o);
}

// ---------------- bias + elu (layer1 epilogue, in place) --------------------
__global__ void bias_elu_kernel(float* __restrict__ y, const float* __restrict__ b, int total) {
    int i = blockIdx.x * blockDim.x + threadIdx.x;
    if (i >= total) return;
    float v = y[i] + b[i & (HC1 - 1)];
    y[i] = v > 0.0f ? v : expm1f(v);
}

// ---------------- final: head mean + bias -----------------------------------
__global__ void final_kernel(const float* __restrict__ acc,
                             const float* __restrict__ b2,
                             float* __restrict__ out, int Nn) {
    int i = blockIdx.x * blockDim.x + threadIdx.x;
    if (i >= Nn * 64) return;
    int n = i >> 6, c = i & 63;
    const float* r = acc + (size_t)n * HC2;
    out[i] = 0.25f * (r[c] + r[64 + c] + r[128 + c] + r[192 + c]) + b2[c];
}

// ---------------- launch ----------------------------------------------------
extern "C" void kernel_launch(void* const* d_in, const int* in_sizes, int n_in,
                              void* d_out, int out_size) {
    const float* x    = (const float*)d_in[0];
    const int*   ei   = (const int*)d_in[1];     // int32 or int64, detected on device
    const float* W1   = (const float*)d_in[2];
    const float* as1  = (const float*)d_in[3];
    const float* ad1  = (const float*)d_in[4];
    const float* b1   = (const float*)d_in[5];
    const float* W2   = (const float*)d_in[6];
    const float* as2  = (const float*)d_in[7];
    const float* ad2  = (const float*)d_in[8];
    const float* b2   = (const float*)d_in[9];
    float*       out  = (float*)d_out;

    const int N  = in_sizes[0] / 128;
    const int E  = in_sizes[1] / 2;
    const int Et = E + N;

    float *p_h1, *p_acc1, *p_h2, *p_acc2, *p_as, *p_ad, *p_mx, *p_sm, *p_e;
    cudaGetSymbolAddress((void**)&p_h1,  g_h1);
    cudaGetSymbolAddress((void**)&p_acc1, g_acc1);
    cudaGetSymbolAddress((void**)&p_h2,  g_h2);
    cudaGetSymbolAddress((void**)&p_acc2, g_acc2);
    cudaGetSymbolAddress((void**)&p_as,  g_asrc);
    cudaGetSymbolAddress((void**)&p_ad,  g_adst);
    cudaGetSymbolAddress((void**)&p_mx,  g_max);
    cudaGetSymbolAddress((void**)&p_sm,  g_sum);
    cudaGetSymbolAddress((void**)&p_e,   g_e);

    const int TB = 256;

    // dtype sniff: must run before any edge kernel
    detect_kernel<<<1, 256>>>((const unsigned int*)ei, (long long)in_sizes[1] * 2);

    // ===== Layer 1 =====
    gemm_kernel<HC1, 8><<<(N + 7) / 8, HC1>>>(x, W1, p_h1, N);
    att_kernel<HC1><<<N, HC1>>>(p_h1, as1, ad1, p_as, p_ad);
    {
        int nAcc = N * HC1, nMS = N * HEADS;
        int mx = nAcc > nMS ? nAcc : nMS;
        init_kernel<<<(mx + TB - 1) / TB, TB>>>(p_acc1, nAcc, p_mx, p_sm, nMS);
    }
    edge_max_kernel<<<(Et + TB - 1) / TB, TB>>>(ei, E, N, p_as, p_ad, p_mx);
    edge_sum_kernel<<<(Et + TB - 1) / TB, TB>>>(ei, E, N, p_as, p_ad, p_mx, p_e, p_sm);
    {
        long long tot = (long long)Et * 32;
        edge_scatter_kernel<HC1, 32><<<(int)((tot + TB - 1) / TB), TB>>>(
            ei, E, N, p_h1, p_e, p_sm, p_acc1);
    }
    bias_elu_kernel<<<(N * HC1 + TB - 1) / TB, TB>>>(p_acc1, b1, N * HC1);

    // ===== Layer 2 =====
    gemm_kernel<HC2, 8><<<(N + 7) / 8, HC2>>>(p_acc1, W2, p_h2, N);
    att_kernel<HC2><<<N, HC2>>>(p_h2, as2, ad2, p_as, p_ad);
    {
        int nAcc = N * HC2, nMS = N * HEADS;
        int mx = nAcc > nMS ? nAcc : nMS;
        init_kernel<<<(mx + TB - 1) / TB, TB>>>(p_acc2, nAcc, p_mx, p_sm, nMS);
    }
    edge_max_kernel<<<(Et + TB - 1) / TB, TB>>>(ei, E, N, p_as, p_ad, p_mx);
    edge_sum_kernel<<<(Et + TB - 1) / TB, TB>>>(ei, E, N, p_as, p_ad, p_mx, p_e, p_sm);
    {
        long long tot = (long long)Et * 64;
        edge_scatter_kernel<HC2, 64><<<(int)((tot + TB - 1) / TB), TB>>>(
            ei, E, N, p_h2, p_e, p_sm, p_acc2);
    }
    final_kernel<<<(N * 64 + TB - 1) / TB, TB>>>(p_acc2, b2, out, N);
}

// round 4
// speedup vs baseline: 1.1419x; 1.1419x over previous
#include <cuda_runtime.h>

// Problem-shape maxima (fixed by the dataset)
#define NMAX   50000
#define EMAX   800000
#define ETMAX  (EMAX + NMAX)      // edges + self loops
#define HEADS  4
#define HC1    128                // heads * 32
#define HC2    256                // heads * 64
#define NEG_SLOPE 0.2f
#define GAT_EPS 1e-16f

// ---------------- scratch (static device globals; no allocation) ------------
__device__ float g_h1 [NMAX * HC1];   // layer1 linear output
__device__ float g_acc1[NMAX * HC1];  // layer1 scatter accumulator -> y1 (elu)
__device__ float g_h2 [NMAX * HC2];   // layer2 linear output
__device__ float g_acc2[NMAX * HC2];  // layer2 scatter accumulator
__device__ float g_asrc[NMAX * HEADS];
__device__ float g_adst[NMAX * HEADS];
__device__ float g_sum [NMAX * HEADS];
__device__ float g_e   [ETMAX * HEADS]; // exp(logit) -> alpha, per edge/head
__device__ int2  g_sd  [ETMAX];         // (src,dst) int32 pairs incl self loops
__device__ int   g_is64;                // 1 if edge_index is int64 on device

// ---------------- helpers ---------------------------------------------------
__device__ __forceinline__ float lrelu(float x) {
    return x > 0.0f ? x : NEG_SLOPE * x;
}

__device__ __forceinline__ int eidx(const int* __restrict__ ei, int is64, long long pos) {
    if (is64) return (int)((const long long*)ei)[pos];
    return ei[pos];
}

__device__ __forceinline__ void red_add_v4(float* p, float4 v) {
    asm volatile("red.global.add.v4.f32 [%0], {%1, %2, %3, %4};"
                 :: "l"(p), "f"(v.x), "f"(v.y), "f"(v.z), "f"(v.w)
                 : "memory");
}

// ---------------- dtype detection -------------------------------------------
__global__ void detect_kernel(const unsigned int* __restrict__ w, long long nWords) {
    __shared__ int s_nz;
    if (threadIdx.x == 0) s_nz = 0;
    __syncthreads();
    long long limit = nWords < 16384 ? nWords : 16384;
    int nz = 0;
    for (long long i = 1 + 2LL * threadIdx.x; i < limit; i += 2LL * blockDim.x)
        nz |= (w[i] != 0u);
    if (nz) atomicOr(&s_nz, 1);
    __syncthreads();
    if (threadIdx.x == 0) g_is64 = (s_nz == 0) ? 1 : 0;
}

// ---------------- build (src,dst) int2 pairs + self loops -------------------
__global__ void prep_kernel(const int* __restrict__ ei, int E, int Nn,
                            int2* __restrict__ sd) {
    int e = blockIdx.x * blockDim.x + threadIdx.x;
    int Et = E + Nn;
    if (e >= Et) return;
    int is64 = g_is64;
    int s, d;
    if (e < E) { s = eidx(ei, is64, e); d = eidx(ei, is64, (long long)E + e); }
    else       { s = d = e - E; }
    sd[e] = make_int2(s, d);
}

// ---------------- tiled GEMM: Y[M,NOUT] = X[M,128] @ W[128,NOUT] ------------
// Block tile 64 x 128, full K=128 staged in smem, 256 threads, 4x8 per thread.
#define XPAD 132
template<int NOUT>
__global__ void gemm_tiled(const float* __restrict__ X,
                           const float* __restrict__ W,
                           float* __restrict__ Y, int M) {
    extern __shared__ float smem[];
    float (*Xs)[XPAD] = (float (*)[XPAD])smem;                 // [64][132]
    float (*Ws)[128]  = (float (*)[128])(smem + 64 * XPAD);    // [128][128]

    const int row0 = blockIdx.x * 64;
    const int c0   = blockIdx.y * 128;
    const int tid  = threadIdx.x;

#pragma unroll
    for (int i = 0; i < 8; i++) {            // 2048 float4 of X tile
        int idx = tid + i * 256;
        int r = idx >> 5, kq = idx & 31;
        float4 v = (row0 + r < M) ? ((const float4*)X)[(size_t)(row0 + r) * 32 + kq]
                                  : make_float4(0.f, 0.f, 0.f, 0.f);
        *(float4*)&Xs[r][kq * 4] = v;
    }
#pragma unroll
    for (int i = 0; i < 16; i++) {           // 4096 float4 of W tile
        int idx = tid + i * 256;
        int k = idx >> 5, cq = idx & 31;
        *(float4*)&Ws[k][cq * 4] =
            *(const float4*)&W[(size_t)k * NOUT + c0 + cq * 4];
    }
    __syncthreads();

    const int tx = tid & 15, ty = tid >> 4;
    float acc[4][8];
#pragma unroll
    for (int ri = 0; ri < 4; ri++)
#pragma unroll
        for (int ci = 0; ci < 8; ci++) acc[ri][ci] = 0.0f;

#pragma unroll 4
    for (int k = 0; k < 128; k++) {
        float4 w0 = *(float4*)&Ws[k][tx * 8];
        float4 w1 = *(float4*)&Ws[k][tx * 8 + 4];
        float xv[4];
#pragma unroll
        for (int ri = 0; ri < 4; ri++) xv[ri] = Xs[ty * 4 + ri][k];
#pragma unroll
        for (int ri = 0; ri < 4; ri++) {
            acc[ri][0] = fmaf(xv[ri], w0.x, acc[ri][0]);
            acc[ri][1] = fmaf(xv[ri], w0.y, acc[ri][1]);
            acc[ri][2] = fmaf(xv[ri], w0.z, acc[ri][2]);
            acc[ri][3] = fmaf(xv[ri], w0.w, acc[ri][3]);
            acc[ri][4] = fmaf(xv[ri], w1.x, acc[ri][4]);
            acc[ri][5] = fmaf(xv[ri], w1.y, acc[ri][5]);
            acc[ri][6] = fmaf(xv[ri], w1.z, acc[ri][6]);
            acc[ri][7] = fmaf(xv[ri], w1.w, acc[ri][7]);
        }
    }

#pragma unroll
    for (int ri = 0; ri < 4; ri++) {
        int r = row0 + ty * 4 + ri;
        if (r < M) {
            float4 o0 = make_float4(acc[ri][0], acc[ri][1], acc[ri][2], acc[ri][3]);
            float4 o1 = make_float4(acc[ri][4], acc[ri][5], acc[ri][6], acc[ri][7]);
            *(float4*)&Y[(size_t)r * NOUT + c0 + tx * 8]     = o0;
            *(float4*)&Y[(size_t)r * NOUT + c0 + tx * 8 + 4] = o1;
        }
    }
}
#define GEMM_SMEM ((64 * XPAD + 128 * 128) * 4)

// ---------------- per-node attention coefficients ---------------------------
template<int HC>
__global__ void att_kernel(const float* __restrict__ H,
                           const float* __restrict__ av_src,
                           const float* __restrict__ av_dst,
                           float* __restrict__ osrc,
                           float* __restrict__ odst) {
    const int n = blockIdx.x;
    const int t = threadIdx.x;
    float v  = H[(size_t)n * HC + t];
    float ps = v * av_src[t];
    float pd = v * av_dst[t];
#pragma unroll
    for (int o = 16; o > 0; o >>= 1) {
        ps += __shfl_down_sync(0xffffffffu, ps, o);
        pd += __shfl_down_sync(0xffffffffu, pd, o);
    }
    __shared__ float ss[HC / 32], sd[HC / 32];
    if ((t & 31) == 0) { ss[t >> 5] = ps; sd[t >> 5] = pd; }
    __syncthreads();
    constexpr int WPH = (HC / HEADS) / 32;
    if (t < HEADS) {
        float s = 0.0f, d = 0.0f;
#pragma unroll
        for (int w = 0; w < WPH; w++) { s += ss[t * WPH + w]; d += sd[t * WPH + w]; }
        osrc[n * HEADS + t] = s;
        odst[n * HEADS + t] = d;
    }
}

// ---------------- vectorized init: acc = 0, sum = 0 -------------------------
__global__ void initv4_kernel(float4* __restrict__ acc, int n4a,
                              float4* __restrict__ sum4, int n4s) {
    int i = blockIdx.x * blockDim.x + threadIdx.x;
    float4 z = make_float4(0.f, 0.f, 0.f, 0.f);
    if (i < n4a) acc[i] = z;
    if (i < n4s) sum4[i] = z;
}

// ---------------- edge pass: exp(logit) + segment sum (no max shift) --------
__global__ void edge_sum_kernel(const int2* __restrict__ sd, int Et,
                                const float* __restrict__ asrc,
                                const float* __restrict__ adst,
                                float* __restrict__ ebuf,
                                float* __restrict__ sm) {
    int e = blockIdx.x * blockDim.x + threadIdx.x;
    if (e >= Et) return;
    int2 p = sd[e];
    float4 as = ((const float4*)asrc)[p.x];
    float4 ad = ((const float4*)adst)[p.y];
    float4 ev;
    ev.x = expf(lrelu(as.x + ad.x));
    ev.y = expf(lrelu(as.y + ad.y));
    ev.z = expf(lrelu(as.z + ad.z));
    ev.w = expf(lrelu(as.w + ad.w));
    ((float4*)ebuf)[e] = ev;
    red_add_v4(&sm[p.y * 4], ev);
}

// ---------------- alpha = e / (sum + eps), once per edge-head ---------------
__global__ void alpha_kernel(const int2* __restrict__ sd, int Et,
                             const float* __restrict__ sm,
                             float* __restrict__ ebuf) {
    int e = blockIdx.x * blockDim.x + threadIdx.x;
    if (e >= Et) return;
    int d = sd[e].y;
    float4 s4 = ((const float4*)sm)[d];
    float4 ev = ((const float4*)ebuf)[e];
    ev.x /= (s4.x + GAT_EPS);
    ev.y /= (s4.y + GAT_EPS);
    ev.z /= (s4.z + GAT_EPS);
    ev.w /= (s4.w + GAT_EPS);
    ((float4*)ebuf)[e] = ev;
}

// ---------------- weighted scatter-add: 2 float4 per lane -------------------
template<int HC, int LPE>
__global__ void edge_scatter_kernel(const int2* __restrict__ sd, int Et,
                                    const float* __restrict__ H,
                                    const float* __restrict__ alpha,
                                    float* __restrict__ acc) {
    long long gt = (long long)blockIdx.x * blockDim.x + threadIdx.x;
    int e = (int)(gt / LPE);
    int L = (int)(gt % LPE);
    if (e >= Et) return;
    int2 p = sd[e];
    constexpr int F4H = (HC / HEADS) / 4;     // float4s per head
    const int f4i  = 2 * L;
    const int head = f4i / F4H;
    float a = __ldg(&alpha[e * 4 + head]);
    const float4* hp = (const float4*)(H + (size_t)p.x * HC);
    float4 v0 = hp[f4i], v1 = hp[f4i + 1];
    float4 o0 = make_float4(a * v0.x, a * v0.y, a * v0.z, a * v0.w);
    float4 o1 = make_float4(a * v1.x, a * v1.y, a * v1.z, a * v1.w);
    float* base = acc + (size_t)p.y * HC + f4i * 4;
    red_add_v4(base, o0);
    red_add_v4(base + 4, o1);
}

// ---------------- bias + elu (layer1 epilogue, in place) --------------------
__global__ void bias_elu_kernel(float* __restrict__ y, const float* __restrict__ b, int total) {
    int i = blockIdx.x * blockDim.x + threadIdx.x;
    if (i >= total) return;
    float v = y[i] + b[i & (HC1 - 1)];
    y[i] = v > 0.0f ? v : expm1f(v);
}

// ---------------- final: head mean + bias -----------------------------------
__global__ void final_kernel(const float* __restrict__ acc,
                             const float* __restrict__ b2,
                             float* __restrict__ out, int Nn) {
    int i = blockIdx.x * blockDim.x + threadIdx.x;
    if (i >= Nn * 64) return;
    int n = i >> 6, c = i & 63;
    const float* r = acc + (size_t)n * HC2;
    out[i] = 0.25f * (r[c] + r[64 + c] + r[128 + c] + r[192 + c]) + b2[c];
}

// ---------------- launch ----------------------------------------------------
extern "C" void kernel_launch(void* const* d_in, const int* in_sizes, int n_in,
                              void* d_out, int out_size) {
    const float* x    = (const float*)d_in[0];
    const int*   ei   = (const int*)d_in[1];
    const float* W1   = (const float*)d_in[2];
    const float* as1  = (const float*)d_in[3];
    const float* ad1  = (const float*)d_in[4];
    const float* b1   = (const float*)d_in[5];
    const float* W2   = (const float*)d_in[6];
    const float* as2  = (const float*)d_in[7];
    const float* ad2  = (const float*)d_in[8];
    const float* b2   = (const float*)d_in[9];
    float*       out  = (float*)d_out;

    const int N  = in_sizes[0] / 128;
    const int E  = in_sizes[1] / 2;
    const int Et = E + N;

    float *p_h1, *p_acc1, *p_h2, *p_acc2, *p_as, *p_ad, *p_sm, *p_e;
    int2  *p_sd;
    cudaGetSymbolAddress((void**)&p_h1,  g_h1);
    cudaGetSymbolAddress((void**)&p_acc1, g_acc1);
    cudaGetSymbolAddress((void**)&p_h2,  g_h2);
    cudaGetSymbolAddress((void**)&p_acc2, g_acc2);
    cudaGetSymbolAddress((void**)&p_as,  g_asrc);
    cudaGetSymbolAddress((void**)&p_ad,  g_adst);
    cudaGetSymbolAddress((void**)&p_sm,  g_sum);
    cudaGetSymbolAddress((void**)&p_e,   g_e);
    cudaGetSymbolAddress((void**)&p_sd,  g_sd);

    static int smem_set = 0;
    if (!smem_set) {
        cudaFuncSetAttribute(gemm_tiled<HC1>, cudaFuncAttributeMaxDynamicSharedMemorySize, GEMM_SMEM);
        cudaFuncSetAttribute(gemm_tiled<HC2>, cudaFuncAttributeMaxDynamicSharedMemorySize, GEMM_SMEM);
        smem_set = 1;
    }

    const int TB = 256;
    const int gemmRows = (N + 63) / 64;

    detect_kernel<<<1, 256>>>((const unsigned int*)ei, (long long)in_sizes[1] * 2);
    prep_kernel<<<(Et + TB - 1) / TB, TB>>>(ei, E, N, p_sd);

    // ===== Layer 1 =====
    gemm_tiled<HC1><<<dim3(gemmRows, 1), 256, GEMM_SMEM>>>(x, W1, p_h1, N);
    att_kernel<HC1><<<N, HC1>>>(p_h1, as1, ad1, p_as, p_ad);
    {
        int n4a = N * HC1 / 4, n4s = N;
        initv4_kernel<<<(n4a + TB - 1) / TB, TB>>>((float4*)p_acc1, n4a, (float4*)p_sm, n4s);
    }
    edge_sum_kernel<<<(Et + TB - 1) / TB, TB>>>(p_sd, Et, p_as, p_ad, p_e, p_sm);
    alpha_kernel<<<(Et + TB - 1) / TB, TB>>>(p_sd, Et, p_sm, p_e);
    {
        long long tot = (long long)Et * 16;
        edge_scatter_kernel<HC1, 16><<<(int)((tot + TB - 1) / TB), TB>>>(p_sd, Et, p_h1, p_e, p_acc1);
    }
    bias_elu_kernel<<<(N * HC1 + TB - 1) / TB, TB>>>(p_acc1, b1, N * HC1);

    // ===== Layer 2 =====
    gemm_tiled<HC2><<<dim3(gemmRows, 2), 256, GEMM_SMEM>>>(p_acc1, W2, p_h2, N);
    att_kernel<HC2><<<N, HC2>>>(p_h2, as2, ad2, p_as, p_ad);
    {
        int n4a = N * HC2 / 4, n4s = N;
        initv4_kernel<<<(n4a + TB - 1) / TB, TB>>>((float4*)p_acc2, n4a, (float4*)p_sm, n4s);
    }
    edge_sum_kernel<<<(Et + TB - 1) / TB, TB>>>(p_sd, Et, p_as, p_ad, p_e, p_sm);
    alpha_kernel<<<(Et + TB - 1) / TB, TB>>>(p_sd, Et, p_sm, p_e);
    {
        long long tot = (long long)Et * 32;
        edge_scatter_kernel<HC2, 32><<<(int)((tot + TB - 1) / TB), TB>>>(p_sd, Et, p_h2, p_e, p_acc2);
    }
    final_kernel<<<(N * 64 + TB - 1) / TB, TB>>>(p_acc2, b2, out, N);
}